// round 1
// baseline (speedup 1.0000x reference)
#include <cuda_runtime.h>
#include <math.h>

// Problem constants
#define BB 4
#define TT 4096
#define DDIM 1024
#define HH 16
#define HD 64
#define NCHUNK 16
#define TCHUNK (TT / NCHUNK)   // 256

// Scratch (device globals: allocation-free rule)
__device__ float g_qkv[(size_t)BB * TT * 3 * DDIM];   // [b,t, 3*1024]   192 MB
__device__ float g_attn[(size_t)BB * TT * DDIM];      // [b,t,d]          64 MB
__device__ float g_kvp[(size_t)NCHUNK * BB * HH * HD * HD]; // partial kv  16 MB
__device__ float g_ksp[(size_t)NCHUNK * BB * HH * HD];      // partial ksum
__device__ float g_kv[BB * HH * HD * HD];
__device__ float g_ksum[BB * HH * HD];

// ---------------------------------------------------------------------------
// SGEMM: C[M,N] = A[M,K] * B[N,K]^T   (both row-major, K contiguous)
// 128x128 tile, BK=8, 8x8 per thread, 256 threads.
// M,N,K all divisible by tile dims here (no bounds checks).
// ---------------------------------------------------------------------------
__global__ __launch_bounds__(256) void sgemm_nt(const float* __restrict__ A,
                                                const float* __restrict__ B,
                                                float* __restrict__ C,
                                                int M, int N, int K) {
    __shared__ float As[8 * 132];
    __shared__ float Bs[8 * 132];
    const int tid = threadIdx.x;
    const int bm = blockIdx.y * 128;
    const int bn = blockIdx.x * 128;
    const int tx = tid & 15;
    const int ty = tid >> 4;
    const int lrow = tid >> 1;
    const int lk = (tid & 1) * 4;
    const float* Ap = A + (size_t)(bm + lrow) * K + lk;
    const float* Bp = B + (size_t)(bn + lrow) * K + lk;

    float acc[8][8];
#pragma unroll
    for (int i = 0; i < 8; i++)
#pragma unroll
        for (int j = 0; j < 8; j++) acc[i][j] = 0.f;

    for (int k0 = 0; k0 < K; k0 += 8) {
        float4 a4 = *(const float4*)(Ap + k0);
        float4 b4 = *(const float4*)(Bp + k0);
        __syncthreads();
        As[(lk + 0) * 132 + lrow] = a4.x;
        As[(lk + 1) * 132 + lrow] = a4.y;
        As[(lk + 2) * 132 + lrow] = a4.z;
        As[(lk + 3) * 132 + lrow] = a4.w;
        Bs[(lk + 0) * 132 + lrow] = b4.x;
        Bs[(lk + 1) * 132 + lrow] = b4.y;
        Bs[(lk + 2) * 132 + lrow] = b4.z;
        Bs[(lk + 3) * 132 + lrow] = b4.w;
        __syncthreads();
#pragma unroll
        for (int kk = 0; kk < 8; kk++) {
            float4 a0 = *(const float4*)&As[kk * 132 + ty * 8];
            float4 a1 = *(const float4*)&As[kk * 132 + ty * 8 + 4];
            float4 b0 = *(const float4*)&Bs[kk * 132 + tx * 8];
            float4 b1 = *(const float4*)&Bs[kk * 132 + tx * 8 + 4];
            float ar[8] = {a0.x, a0.y, a0.z, a0.w, a1.x, a1.y, a1.z, a1.w};
            float br[8] = {b0.x, b0.y, b0.z, b0.w, b1.x, b1.y, b1.z, b1.w};
#pragma unroll
            for (int i = 0; i < 8; i++)
#pragma unroll
                for (int j = 0; j < 8; j++)
                    acc[i][j] = fmaf(ar[i], br[j], acc[i][j]);
        }
    }
#pragma unroll
    for (int i = 0; i < 8; i++) {
        float* Cp = C + (size_t)(bm + ty * 8 + i) * N + bn + tx * 8;
        *(float4*)Cp = make_float4(acc[i][0], acc[i][1], acc[i][2], acc[i][3]);
        *(float4*)(Cp + 4) = make_float4(acc[i][4], acc[i][5], acc[i][6], acc[i][7]);
    }
}

// ---------------------------------------------------------------------------
// kv partial accumulation: per (b,h, t-chunk) block computes
//   kv[d][v] = sum_t kfeat[t][d] * v[t][v],  ksum[d] = sum_t kfeat[t][d]
// kfeat = elu(rope(k)) + 1 computed inline. Deterministic (no atomics):
// partials written to g_kvp / g_ksp, reduced in fixed order afterwards.
// ---------------------------------------------------------------------------
__global__ __launch_bounds__(256) void kv_accum() {
    const int bh = blockIdx.x;             // 0..63
    const int b = bh >> 4, h = bh & 15;
    const int chunk = blockIdx.y;          // 0..15
    const int t0 = chunk * TCHUNK;
    const int tid = threadIdx.x;
    const int d = tid & 63, grp = tid >> 6;

    __shared__ float vsh[64];
    __shared__ float kf[64];

    float invf = 0.f;
    if (tid < 32) invf = expf(-9.210340371976184f * (float)tid / 32.f); // 10000^(-i/32)

    float acc[16];
#pragma unroll
    for (int j = 0; j < 16; j++) acc[j] = 0.f;
    float ksum_local = 0.f;

    for (int t = t0; t < t0 + TCHUNK; ++t) {
        const float* base = g_qkv + ((size_t)(b * TT + t)) * 3072 + h * 64;
        if (tid < 32) {
            float kx = base[1024 + tid];
            float ky = base[1024 + tid + 32];
            float s, c;
            sincosf((float)t * invf, &s, &c);
            float re = kx * c - ky * s;
            float ro = kx * s + ky * c;
            kf[tid]      = re > 0.f ? re + 1.f : expf(re);
            kf[tid + 32] = ro > 0.f ? ro + 1.f : expf(ro);
        } else if (tid >= 64 && tid < 128) {
            vsh[tid - 64] = base[2048 + tid - 64];
        }
        __syncthreads();
        float kd = kf[d];
        if (grp == 0) ksum_local += kd;
        const float* vv = vsh + grp * 16;
#pragma unroll
        for (int j = 0; j < 16; j++) acc[j] = fmaf(kd, vv[j], acc[j]);
        __syncthreads();
    }

    float* kvout = g_kvp + ((size_t)chunk * 64 + bh) * 4096;
#pragma unroll
    for (int j = 0; j < 16; j++) kvout[d * 64 + grp * 16 + j] = acc[j];
    if (grp == 0) g_ksp[((size_t)chunk * 64 + bh) * 64 + d] = ksum_local;
}

// Fixed-order reduction of partials (deterministic).
__global__ __launch_bounds__(256) void kv_reduce() {
    int i = blockIdx.x * 256 + threadIdx.x;
    if (i < BB * HH * HD * HD) {
        float s = 0.f;
#pragma unroll
        for (int c = 0; c < NCHUNK; c++) s += g_kvp[(size_t)c * (BB * HH * HD * HD) + i];
        g_kv[i] = s;
    }
    if (i < BB * HH * HD) {
        float s = 0.f;
#pragma unroll
        for (int c = 0; c < NCHUNK; c++) s += g_ksp[(size_t)c * (BB * HH * HD) + i];
        g_ksum[i] = s;
    }
}

// ---------------------------------------------------------------------------
// Output attention: out[b,t,h,v] = (qfeat . kv[:,v]) / max(qfeat . ksum, 1e-6)
// qfeat = elu(rope(q) * hd^-0.5) + 1 computed inline.
// Block = (bh, t-chunk of 256); 256 threads process 4 timesteps at once
// (tg = timestep lane group, v = output column).
// ---------------------------------------------------------------------------
__global__ __launch_bounds__(256) void attn_out() {
    const int bh = blockIdx.x;
    const int b = bh >> 4, h = bh & 15;
    const int t0 = blockIdx.y * TCHUNK;
    const int tid = threadIdx.x;
    const int tg = tid >> 6, v = tid & 63;

    __shared__ float kvsh[64 * 64];
    __shared__ float ks[64];
    __shared__ float qf[4][64];
    __shared__ float invs[32];

    for (int i = tid; i < 4096; i += 256) kvsh[i] = g_kv[bh * 4096 + i];
    if (tid < 64) ks[tid] = g_ksum[bh * 64 + tid];
    if (tid < 32) invs[tid] = expf(-9.210340371976184f * (float)tid / 32.f);
    __syncthreads();

    for (int t4 = t0; t4 < t0 + TCHUNK; t4 += 4) {
        int t = t4 + tg;
        const float* qrow = g_qkv + ((size_t)(b * TT + t)) * 3072 + h * 64;
        if (v < 32) {
            float s, c;
            sincosf((float)t * invs[v], &s, &c);
            float qx = qrow[v], qy = qrow[v + 32];
            float re = (qx * c - qy * s) * 0.125f;   // scale = hd^-0.5 = 0.125
            float ro = (qx * s + qy * c) * 0.125f;
            qf[tg][v]      = re > 0.f ? re + 1.f : expf(re);
            qf[tg][v + 32] = ro > 0.f ? ro + 1.f : expf(ro);
        }
        __syncthreads();
        float denom = 0.f, o = 0.f;
#pragma unroll 16
        for (int dd = 0; dd < 64; dd++) {
            float qv = qf[tg][dd];
            denom = fmaf(qv, ks[dd], denom);
            o = fmaf(qv, kvsh[dd * 64 + v], o);
        }
        denom = fmaxf(denom, 1e-6f);
        g_attn[((size_t)(b * TT + t)) * DDIM + h * 64 + v] = o / denom;
        __syncthreads();
    }
}

// ---------------------------------------------------------------------------
extern "C" void kernel_launch(void* const* d_in, const int* in_sizes, int n_in,
                              void* d_out, int out_size) {
    const float* x    = (const float*)d_in[0];   // [4,4096,1024]
    const float* wqkv = (const float*)d_in[1];   // [3072,1024]
    const float* wout = (const float*)d_in[2];   // [1024,1024]
    float* out = (float*)d_out;                  // [4,4096,1024]

    void* p_qkv = nullptr;
    void* p_attn = nullptr;
    cudaGetSymbolAddress(&p_qkv, g_qkv);
    cudaGetSymbolAddress(&p_attn, g_attn);

    // 1) qkv = x @ w_qkv^T   [16384 x 3072]
    sgemm_nt<<<dim3(3072 / 128, 16384 / 128), 256>>>(x, wqkv, (float*)p_qkv,
                                                     BB * TT, 3 * DDIM, DDIM);
    // 2) kv/ksum partial accumulation + deterministic reduce
    kv_accum<<<dim3(BB * HH, NCHUNK), 256>>>();
    kv_reduce<<<(BB * HH * HD * HD + 255) / 256, 256>>>();
    // 3) attention output (fused q rope + elu feature map)
    attn_out<<<dim3(BB * HH, NCHUNK), 256>>>();
    // 4) final projection: out = attn @ w_out^T  [16384 x 1024]
    sgemm_nt<<<dim3(1024 / 128, 16384 / 128), 256>>>((const float*)p_attn, wout, out,
                                                     BB * TT, DDIM, DDIM);
}

// round 3
// speedup vs baseline: 1.6168x; 1.6168x over previous
#include <cuda_runtime.h>
#include <cuda_bf16.h>
#include <cstdint>
#include <math.h>

// Problem constants
#define BB 4
#define TT 4096
#define DDIM 1024
#define HH 16
#define HD 64
#define NCHUNK 16
#define TCHUNK (TT / NCHUNK)   // 256

// Scratch (device globals: allocation-free rule)
__device__ float g_qkv[(size_t)BB * TT * 3 * DDIM];   // [b,t, 3*1024]   192 MB
__device__ float g_attn[(size_t)BB * TT * DDIM];      // [b,t,d]          64 MB
__device__ float g_kvp[(size_t)NCHUNK * BB * HH * HD * HD]; // partial kv  16 MB
__device__ float g_ksp[(size_t)NCHUNK * BB * HH * HD];      // partial ksum
__device__ float g_kv[BB * HH * HD * HD];
__device__ float g_ksum[BB * HH * HD];

// ---------------------------------------------------------------------------
// Tensor-core GEMM with 3-term bf16 split (Ah*Bh + Ah*Bl + Al*Bh).
// C[M,N] = A[M,K] * B[N,K]^T, fp32 in/out, effective precision ~2^-16.
// 128x128x32 CTA tile, 8 warps (64x32 warp tile), mma.sync m16n8k16 bf16.
// ---------------------------------------------------------------------------
#define Bb_M 128
#define Bb_N 128
#define Bb_K 32
#define LDSE 40   // BK + 8 bf16 pad -> 80B row stride, conflict-free ldmatrix

__device__ __forceinline__ uint32_t saddr(const void* p) {
    return (uint32_t)__cvta_generic_to_shared(p);
}
__device__ __forceinline__ void ldm_x4(uint32_t (&r)[4], uint32_t a) {
    asm volatile("ldmatrix.sync.aligned.m8n8.x4.shared.b16 {%0,%1,%2,%3}, [%4];"
                 : "=r"(r[0]), "=r"(r[1]), "=r"(r[2]), "=r"(r[3]) : "r"(a));
}
__device__ __forceinline__ void ldm_x2(uint32_t (&r)[2], uint32_t a) {
    asm volatile("ldmatrix.sync.aligned.m8n8.x2.shared.b16 {%0,%1}, [%2];"
                 : "=r"(r[0]), "=r"(r[1]) : "r"(a));
}
__device__ __forceinline__ void mma16816(float (&c)[4], const uint32_t (&a)[4],
                                         const uint32_t (&b)[2]) {
    asm volatile(
        "mma.sync.aligned.m16n8k16.row.col.f32.bf16.bf16.f32 "
        "{%0,%1,%2,%3}, {%4,%5,%6,%7}, {%8,%9}, {%0,%1,%2,%3};"
        : "+f"(c[0]), "+f"(c[1]), "+f"(c[2]), "+f"(c[3])
        : "r"(a[0]), "r"(a[1]), "r"(a[2]), "r"(a[3]), "r"(b[0]), "r"(b[1]));
}

__global__ __launch_bounds__(256) void gemm_bf16x3(const float* __restrict__ A,
                                                   const float* __restrict__ B,
                                                   float* __restrict__ C,
                                                   int M, int N, int K) {
    __shared__ alignas(16) __nv_bfloat16 sAh[Bb_M * LDSE];
    __shared__ alignas(16) __nv_bfloat16 sAl[Bb_M * LDSE];
    __shared__ alignas(16) __nv_bfloat16 sBh[Bb_N * LDSE];
    __shared__ alignas(16) __nv_bfloat16 sBl[Bb_N * LDSE];

    const int tid = threadIdx.x;
    const int bm = blockIdx.y * Bb_M;
    const int bn = blockIdx.x * Bb_N;

    // global loader mapping: thread -> (row = tid/2, 16-col half = tid&1), 4x float4
    const int lrow = tid >> 1;
    const int lcol = (tid & 1) * 16;
    const float* Ap = A + (size_t)(bm + lrow) * K + lcol;
    const float* Bp = B + (size_t)(bn + lrow) * K + lcol;

    const int warp = tid >> 5, lane = tid & 31;
    const int wm = (warp >> 2) * 64;   // 0 or 64
    const int wn = (warp & 3) * 32;    // 0,32,64,96

    float acc[4][4][4];
#pragma unroll
    for (int mi = 0; mi < 4; mi++)
#pragma unroll
        for (int ni = 0; ni < 4; ni++)
#pragma unroll
            for (int j = 0; j < 4; j++) acc[mi][ni][j] = 0.f;

    float4 ra[4], rb[4];
#pragma unroll
    for (int i = 0; i < 4; i++) {
        ra[i] = *(const float4*)(Ap + i * 4);
        rb[i] = *(const float4*)(Bp + i * 4);
    }

    // precomputed ldmatrix smem coordinates
    const int arow = lane & 15, acol8 = (lane >> 4) * 8;
    const int brow = lane & 7, bcol8 = ((lane >> 3) & 1) * 8;

    for (int kt = 0; kt < K; kt += Bb_K) {
        // stage current regs -> smem with hi/lo bf16 split
#pragma unroll
        for (int i = 0; i < 4; i++) {
            const float* av = (const float*)&ra[i];
            const float* bv = (const float*)&rb[i];
#pragma unroll
            for (int j = 0; j < 4; j++) {
                int idx = lrow * LDSE + lcol + i * 4 + j;
                float va = av[j];
                __nv_bfloat16 ha = __float2bfloat16(va);
                sAh[idx] = ha;
                sAl[idx] = __float2bfloat16(va - __bfloat162float(ha));
                float vb = bv[j];
                __nv_bfloat16 hb = __float2bfloat16(vb);
                sBh[idx] = hb;
                sBl[idx] = __float2bfloat16(vb - __bfloat162float(hb));
            }
        }
        __syncthreads();

        // prefetch next tile while tensor cores chew on this one
        if (kt + Bb_K < K) {
#pragma unroll
            for (int i = 0; i < 4; i++) {
                ra[i] = *(const float4*)(Ap + kt + Bb_K + i * 4);
                rb[i] = *(const float4*)(Bp + kt + Bb_K + i * 4);
            }
        }

#pragma unroll
        for (int s = 0; s < 2; s++) {
            uint32_t ah[4][4], al[4][4], bh[4][2], bl[4][2];
#pragma unroll
            for (int mi = 0; mi < 4; mi++) {
                int off = (wm + mi * 16 + arow) * LDSE + s * 16 + acol8;
                ldm_x4(ah[mi], saddr(sAh + off));
                ldm_x4(al[mi], saddr(sAl + off));
            }
#pragma unroll
            for (int ni = 0; ni < 4; ni++) {
                int off = (wn + ni * 8 + brow) * LDSE + s * 16 + bcol8;
                ldm_x2(bh[ni], saddr(sBh + off));
                ldm_x2(bl[ni], saddr(sBl + off));
            }
#pragma unroll
            for (int mi = 0; mi < 4; mi++)
#pragma unroll
                for (int ni = 0; ni < 4; ni++) {
                    mma16816(acc[mi][ni], ah[mi], bh[ni]);
                    mma16816(acc[mi][ni], ah[mi], bl[ni]);
                    mma16816(acc[mi][ni], al[mi], bh[ni]);
                }
        }
        __syncthreads();
    }

    // epilogue: c0,c1 -> (row, col..col+1), c2,c3 -> (row+8, ...)
#pragma unroll
    for (int mi = 0; mi < 4; mi++) {
#pragma unroll
        for (int ni = 0; ni < 4; ni++) {
            int row = bm + wm + mi * 16 + (lane >> 2);
            int col = bn + wn + ni * 8 + (lane & 3) * 2;
            float2* p0 = (float2*)(C + (size_t)row * N + col);
            float2* p1 = (float2*)(C + (size_t)(row + 8) * N + col);
            *p0 = make_float2(acc[mi][ni][0], acc[mi][ni][1]);
            *p1 = make_float2(acc[mi][ni][2], acc[mi][ni][3]);
        }
    }
}

// ---------------------------------------------------------------------------
// kv partial accumulation (unchanged, deterministic)
// ---------------------------------------------------------------------------
__global__ __launch_bounds__(256) void kv_accum() {
    const int bh = blockIdx.x;
    const int b = bh >> 4, h = bh & 15;
    const int chunk = blockIdx.y;
    const int t0 = chunk * TCHUNK;
    const int tid = threadIdx.x;
    const int d = tid & 63, grp = tid >> 6;

    __shared__ float vsh[64];
    __shared__ float kf[64];

    float invf = 0.f;
    if (tid < 32) invf = expf(-9.210340371976184f * (float)tid / 32.f);

    float acc[16];
#pragma unroll
    for (int j = 0; j < 16; j++) acc[j] = 0.f;
    float ksum_local = 0.f;

    for (int t = t0; t < t0 + TCHUNK; ++t) {
        const float* base = g_qkv + ((size_t)(b * TT + t)) * 3072 + h * 64;
        if (tid < 32) {
            float kx = base[1024 + tid];
            float ky = base[1024 + tid + 32];
            float s, c;
            sincosf((float)t * invf, &s, &c);
            float re = kx * c - ky * s;
            float ro = kx * s + ky * c;
            kf[tid]      = re > 0.f ? re + 1.f : expf(re);
            kf[tid + 32] = ro > 0.f ? ro + 1.f : expf(ro);
        } else if (tid >= 64 && tid < 128) {
            vsh[tid - 64] = base[2048 + tid - 64];
        }
        __syncthreads();
        float kd = kf[d];
        if (grp == 0) ksum_local += kd;
        const float* vv = vsh + grp * 16;
#pragma unroll
        for (int j = 0; j < 16; j++) acc[j] = fmaf(kd, vv[j], acc[j]);
        __syncthreads();
    }

    float* kvout = g_kvp + ((size_t)chunk * 64 + bh) * 4096;
#pragma unroll
    for (int j = 0; j < 16; j++) kvout[d * 64 + grp * 16 + j] = acc[j];
    if (grp == 0) g_ksp[((size_t)chunk * 64 + bh) * 64 + d] = ksum_local;
}

__global__ __launch_bounds__(256) void kv_reduce() {
    int i = blockIdx.x * 256 + threadIdx.x;
    if (i < BB * HH * HD * HD) {
        float s = 0.f;
#pragma unroll
        for (int c = 0; c < NCHUNK; c++) s += g_kvp[(size_t)c * (BB * HH * HD * HD) + i];
        g_kv[i] = s;
    }
    if (i < BB * HH * HD) {
        float s = 0.f;
#pragma unroll
        for (int c = 0; c < NCHUNK; c++) s += g_ksp[(size_t)c * (BB * HH * HD) + i];
        g_ksum[i] = s;
    }
}

// ---------------------------------------------------------------------------
// Output attention (unchanged)
// ---------------------------------------------------------------------------
__global__ __launch_bounds__(256) void attn_out() {
    const int bh = blockIdx.x;
    const int b = bh >> 4, h = bh & 15;
    const int t0 = blockIdx.y * TCHUNK;
    const int tid = threadIdx.x;
    const int tg = tid >> 6, v = tid & 63;

    __shared__ float kvsh[64 * 64];
    __shared__ float ks[64];
    __shared__ float qf[4][64];
    __shared__ float invs[32];

    for (int i = tid; i < 4096; i += 256) kvsh[i] = g_kv[bh * 4096 + i];
    if (tid < 64) ks[tid] = g_ksum[bh * 64 + tid];
    if (tid < 32) invs[tid] = expf(-9.210340371976184f * (float)tid / 32.f);
    __syncthreads();

    for (int t4 = t0; t4 < t0 + TCHUNK; t4 += 4) {
        int t = t4 + tg;
        const float* qrow = g_qkv + ((size_t)(b * TT + t)) * 3072 + h * 64;
        if (v < 32) {
            float s, c;
            sincosf((float)t * invs[v], &s, &c);
            float qx = qrow[v], qy = qrow[v + 32];
            float re = (qx * c - qy * s) * 0.125f;
            float ro = (qx * s + qy * c) * 0.125f;
            qf[tg][v]      = re > 0.f ? re + 1.f : expf(re);
            qf[tg][v + 32] = ro > 0.f ? ro + 1.f : expf(ro);
        }
        __syncthreads();
        float denom = 0.f, o = 0.f;
#pragma unroll 16
        for (int dd = 0; dd < 64; dd++) {
            float qv = qf[tg][dd];
            denom = fmaf(qv, ks[dd], denom);
            o = fmaf(qv, kvsh[dd * 64 + v], o);
        }
        denom = fmaxf(denom, 1e-6f);
        g_attn[((size_t)(b * TT + t)) * DDIM + h * 64 + v] = o / denom;
        __syncthreads();
    }
}

// ---------------------------------------------------------------------------
extern "C" void kernel_launch(void* const* d_in, const int* in_sizes, int n_in,
                              void* d_out, int out_size) {
    const float* x    = (const float*)d_in[0];   // [4,4096,1024]
    const float* wqkv = (const float*)d_in[1];   // [3072,1024]
    const float* wout = (const float*)d_in[2];   // [1024,1024]
    float* out = (float*)d_out;                  // [4,4096,1024]

    void* p_qkv = nullptr;
    void* p_attn = nullptr;
    cudaGetSymbolAddress(&p_qkv, g_qkv);
    cudaGetSymbolAddress(&p_attn, g_attn);

    // 1) qkv = x @ w_qkv^T   [16384 x 3072]
    gemm_bf16x3<<<dim3(3072 / Bb_N, 16384 / Bb_M), 256>>>(x, wqkv, (float*)p_qkv,
                                                          BB * TT, 3 * DDIM, DDIM);
    // 2) kv/ksum partial accumulation + deterministic reduce
    kv_accum<<<dim3(BB * HH, NCHUNK), 256>>>();
    kv_reduce<<<(BB * HH * HD * HD + 255) / 256, 256>>>();
    // 3) attention output (fused q rope + elu feature map)
    attn_out<<<dim3(BB * HH, NCHUNK), 256>>>();
    // 4) final projection: out = attn @ w_out^T  [16384 x 1024]
    gemm_bf16x3<<<dim3(1024 / Bb_N, 16384 / Bb_M), 256>>>((const float*)p_attn, wout, out,
                                                          BB * TT, DDIM, DDIM);
}